// round 3
// baseline (speedup 1.0000x reference)
#include <cuda_runtime.h>

#define N 512

// Scratch: sim matrix + scalar accumulator (no allocations allowed).
__device__ float d_sim[N * N];
__device__ float d_acc;

// sigmoid(diff/0.01) with the reference's +/-50 clip on the argument.
// sigmoid(x) = 0.5 + 0.5*tanh(x/2); tanh.approx saturates to +/-1 exactly
// where the clipped sigmoid is 1 or 0 to within 2e-22, so the clip is free.
__device__ __forceinline__ float sig100(float diff) {
    float t;
    asm("tanh.approx.f32 %0, %1;" : "=f"(t) : "f"(50.0f * diff));
    return fmaf(0.5f, t, 0.5f);
}

// --- Kernel 1: sim = P * P^T  (512x512x512 f32 GEMM, NT) -------------------
// 16x16 grid of 32x32 output tiles, 32x8 threads, 4 rows per thread.
__global__ void gemm_nt_kernel(const float* __restrict__ P) {
    __shared__ float As[32][33];
    __shared__ float Bs[32][33];
    const int tx = threadIdx.x;            // 0..31 -> output col within tile
    const int ty = threadIdx.y;            // 0..7
    const int row0 = blockIdx.y * 32;
    const int col0 = blockIdx.x * 32;

    float acc[4] = {0.f, 0.f, 0.f, 0.f};

    for (int d0 = 0; d0 < N; d0 += 32) {
        #pragma unroll
        for (int r = ty; r < 32; r += 8) {
            As[r][tx] = P[(row0 + r) * N + d0 + tx];
            Bs[r][tx] = P[(col0 + r) * N + d0 + tx];
        }
        __syncthreads();
        #pragma unroll
        for (int d = 0; d < 32; d++) {
            float b = Bs[tx][d];
            #pragma unroll
            for (int m = 0; m < 4; m++)
                acc[m] = fmaf(As[ty + 8 * m][d], b, acc[m]);
        }
        __syncthreads();
    }
    #pragma unroll
    for (int m = 0; m < 4; m++)
        d_sim[(row0 + ty + 8 * m) * N + col0 + tx] = acc[m];
}

// --- Kernel 2: zero the accumulator ---------------------------------------
__global__ void init_kernel() { d_acc = 0.0f; }

// --- Kernel 3: main SmoothAP body -----------------------------------------
// One block per anchor i (512 blocks), one thread per j (512 threads).
// Shared: sim row s[512] and positive-mask pos[512]; inner k-loop is
// SMEM-broadcast + MUFU.TANH, fully compute-bound.
// NOTE: labels are int32 (JAX x64 disabled downcasts the requested int64).
__global__ __launch_bounds__(N) void smoothap_kernel(const int* __restrict__ labels) {
    const int i = blockIdx.x;
    const int j = threadIdx.x;

    __shared__ float s[N];
    __shared__ float pos[N];
    __shared__ float2 wred[16];

    const int li = labels[i];
    s[j] = d_sim[i * N + j];
    pos[j] = (labels[j] == li && j != i) ? 1.0f : 0.0f;
    __syncthreads();

    const float sj = s[j];
    float sum_all = 0.0f;
    float sum_pos = 0.0f;

    const float4* s4 = reinterpret_cast<const float4*>(s);
    const float4* p4 = reinterpret_cast<const float4*>(pos);

    #pragma unroll 4
    for (int k4 = 0; k4 < N / 4; k4++) {
        const float4 sv = s4[k4];
        const float4 pv = p4[k4];
        const int kb = k4 * 4;

        float g0 = sig100(sv.x - sj); g0 = (kb + 0 == j) ? 0.0f : g0;
        float g1 = sig100(sv.y - sj); g1 = (kb + 1 == j) ? 0.0f : g1;
        float g2 = sig100(sv.z - sj); g2 = (kb + 2 == j) ? 0.0f : g2;
        float g3 = sig100(sv.w - sj); g3 = (kb + 3 == j) ? 0.0f : g3;

        sum_all += (g0 + g1) + (g2 + g3);
        sum_pos = fmaf(g0, pv.x, sum_pos);
        sum_pos = fmaf(g1, pv.y, sum_pos);
        sum_pos = fmaf(g2, pv.z, sum_pos);
        sum_pos = fmaf(g3, pv.w, sum_pos);
    }

    const float pj = pos[j];
    const float sim_all = 1.0f + sum_all;                      // 1 + sum_k sig
    const float sim_posn = ((j == i) ? 1.0f : 0.0f)
                         + pj * (1.0f + sum_pos);              // eye + I_pos*(1+pos_sum)
    float ratio = sim_posn / sim_all;

    // Block reduction of (ratio, pj) over j.
    float2 v = make_float2(ratio, pj);
    #pragma unroll
    for (int o = 16; o; o >>= 1) {
        v.x += __shfl_xor_sync(0xFFFFFFFFu, v.x, o);
        v.y += __shfl_xor_sync(0xFFFFFFFFu, v.y, o);
    }
    const int w = j >> 5, l = j & 31;
    if (l == 0) wred[w] = v;
    __syncthreads();
    if (w == 0) {
        float2 t = (l < 16) ? wred[l] : make_float2(0.0f, 0.0f);
        #pragma unroll
        for (int o = 8; o; o >>= 1) {
            t.x += __shfl_xor_sync(0xFFFFFFFFu, t.x, o);
            t.y += __shfl_xor_sync(0xFFFFFFFFu, t.y, o);
        }
        if (l == 0) {
            const float n_pos = t.y + 1.0f;
            const float pa = (n_pos > 1.0f) ? (t.x / n_pos) : 0.0f;
            atomicAdd(&d_acc, pa);
        }
    }
}

// --- Kernel 4: finalize ----------------------------------------------------
__global__ void final_kernel(float* __restrict__ out) {
    out[0] = 1.0f - d_acc / (float)N;
}

extern "C" void kernel_launch(void* const* d_in, const int* in_sizes, int n_in,
                              void* d_out, int out_size) {
    const float* preds = (const float*)d_in[0];
    const int* labels = (const int*)d_in[1];
    float* out = (float*)d_out;

    dim3 gthreads(32, 8);
    dim3 gblocks(N / 32, N / 32);
    gemm_nt_kernel<<<gblocks, gthreads>>>(preds);
    init_kernel<<<1, 1>>>();
    smoothap_kernel<<<N, N>>>(labels);
    final_kernel<<<1, 1>>>(out);
}

// round 4
// speedup vs baseline: 2.0743x; 2.0743x over previous
#include <cuda_runtime.h>

#define N 512
#define NB 256

// Scratch (no allocations allowed): sim matrix, scalar accumulator, ticket.
__device__ float d_sim[N * N];
__device__ float d_acc;
__device__ unsigned d_done;   // zero-init; atomicInc wraps back to 0 each replay

// sigmoid(diff/0.01) with the reference's +/-50 clip on the argument.
// sigmoid(x) = 0.5 + 0.5*tanh(x/2); tanh.approx saturates exactly where the
// clipped sigmoid is 1 or 0 (to within 2e-22), so the clip is free.
__device__ __forceinline__ float sig100(float diff) {
    float t;
    asm("tanh.approx.f32 %0, %1;" : "=f"(t) : "f"(50.0f * diff));
    return fmaf(0.5f, t, 0.5f);
}

// --- Kernel 1: sim = P * P^T  (512x512x512 f32 GEMM, NT) -------------------
// 16x16 grid of 32x32 output tiles, 32x8 threads, 4 rows per thread.
// Also zeroes the scalar accumulator for this replay (block boundary sync
// guarantees it lands before any smoothap atomicAdd).
__global__ void gemm_nt_kernel(const float* __restrict__ P) {
    if (blockIdx.x == 0 && blockIdx.y == 0 && threadIdx.x == 0 && threadIdx.y == 0)
        d_acc = 0.0f;

    __shared__ float As[32][33];
    __shared__ float Bs[32][33];
    const int tx = threadIdx.x;            // 0..31 -> output col within tile
    const int ty = threadIdx.y;            // 0..7
    const int row0 = blockIdx.y * 32;
    const int col0 = blockIdx.x * 32;

    float acc[4] = {0.f, 0.f, 0.f, 0.f};

    for (int d0 = 0; d0 < N; d0 += 32) {
        #pragma unroll
        for (int r = ty; r < 32; r += 8) {
            As[r][tx] = P[(row0 + r) * N + d0 + tx];
            Bs[r][tx] = P[(col0 + r) * N + d0 + tx];
        }
        __syncthreads();
        #pragma unroll
        for (int d = 0; d < 32; d++) {
            float b = Bs[tx][d];
            #pragma unroll
            for (int m = 0; m < 4; m++)
                acc[m] = fmaf(As[ty + 8 * m][d], b, acc[m]);
        }
        __syncthreads();
    }
    #pragma unroll
    for (int m = 0; m < 4; m++)
        d_sim[(row0 + ty + 8 * m) * N + col0 + tx] = acc[m];
}

// --- Kernel 2: SmoothAP body, positives-only ------------------------------
// Key identity: sim_pos_rk[i,j] == 0 unless j == i or labels[j] == labels[i].
// So per anchor we need sum_all (and sum_pos) only for the ~9 such j's, not
// all 512: 512*9*512 ~ 2.4e6 sigmoids instead of 512^3 = 1.34e8.
// One block per anchor i; each warp owns one needed j and reduces over k.
// Last block (ticket) writes the final scalar.
__global__ __launch_bounds__(NB) void smoothap_kernel(const int* __restrict__ labels,
                                                      float* __restrict__ out) {
    const int i = blockIdx.x;
    const int t = threadIdx.x;

    __shared__ float s[N];       // sim row i
    __shared__ float pflag[N];   // positive mask (1/0)
    __shared__ int   jlist[N];   // jlist[0] = i, then positive indices
    __shared__ int   cnt;        // m+1
    __shared__ float ssum;       // sum of ratios over needed j

    if (t == 0) { cnt = 1; ssum = 0.0f; jlist[0] = i; }
    __syncthreads();

    const int li = labels[i];
    #pragma unroll
    for (int k = t; k < N; k += NB) {
        s[k] = d_sim[i * N + k];
        const bool p = (labels[k] == li) && (k != i);
        pflag[k] = p ? 1.0f : 0.0f;
        if (p) { int idx = atomicAdd(&cnt, 1); jlist[idx] = k; }
    }
    __syncthreads();

    const int m1 = cnt;                 // n_pos = m + 1
    const int lane = t & 31, w = t >> 5;

    for (int jj = w; jj < m1; jj += NB / 32) {
        const int j = jlist[jj];
        const float sj = s[j];
        float sa = 0.0f, sp = 0.0f;
        #pragma unroll
        for (int it = 0; it < N / 32; it++) {
            const int k = lane + it * 32;
            float g = sig100(s[k] - sj);
            g = (k == j) ? 0.0f : g;    // (1-eye)[j,k] mask
            sa += g;
            sp = fmaf(g, pflag[k], sp);
        }
        #pragma unroll
        for (int o = 16; o; o >>= 1) {
            sa += __shfl_xor_sync(0xFFFFFFFFu, sa, o);
            sp += __shfl_xor_sync(0xFFFFFFFFu, sp, o);
        }
        if (lane == 0) {
            // j==i: sim_pos=1 (eye). j positive: sim_pos = 1 + pos_sum.
            const float ratio = (jj == 0) ? 1.0f / (1.0f + sa)
                                          : (1.0f + sp) / (1.0f + sa);
            atomicAdd(&ssum, ratio);
        }
    }
    __syncthreads();

    if (t == 0) {
        const float pa = (m1 > 1) ? ssum / (float)m1 : 0.0f;  // where(n_pos>1)
        atomicAdd(&d_acc, pa);
        __threadfence();
        const unsigned old = atomicInc(&d_done, N - 1);       // wraps to 0
        if (old == N - 1) {
            const float acc = atomicAdd(&d_acc, 0.0f);        // coherent read
            out[0] = 1.0f - acc / (float)N;
        }
    }
}

extern "C" void kernel_launch(void* const* d_in, const int* in_sizes, int n_in,
                              void* d_out, int out_size) {
    const float* preds = (const float*)d_in[0];
    const int* labels = (const int*)d_in[1];
    float* out = (float*)d_out;

    dim3 gthreads(32, 8);
    dim3 gblocks(N / 32, N / 32);
    gemm_nt_kernel<<<gblocks, gthreads>>>(preds);
    smoothap_kernel<<<N, NB>>>(labels, out);
}

// round 8
// speedup vs baseline: 3.7888x; 1.8265x over previous
#include <cuda_runtime.h>

#define N 512
#define NB 256
#define KC 16          // k-chunk
#define NCHUNK (N / KC)
#define NTILE 16       // 512/32 tile grid
#define NBLK (NTILE * (NTILE + 1) / 2)   // 136 upper-triangle blocks
#define PAD 36         // SMEM row stride in floats: 144B = 16B-aligned for LDS.128

// Scratch (no allocations allowed): sim matrix, scalar accumulator, ticket.
__device__ float d_sim[N * N];
__device__ float d_acc;
__device__ unsigned d_done;   // zero-init; atomicInc wraps back to 0 each replay

// sigmoid(diff/0.01): sigmoid(x) = 0.5 + 0.5*tanh(x/2); tanh.approx saturates
// exactly where the reference's clipped sigmoid is 0/1, so the clip is free.
__device__ __forceinline__ float sig100(float diff) {
    float t;
    asm("tanh.approx.f32 %0, %1;" : "=f"(t) : "f"(50.0f * diff));
    return fmaf(0.5f, t, 0.5f);
}

// --- Kernel 1: symmetric SGEMM sim = P*P^T ---------------------------------
// Upper-triangle 32x32 tiles, 136 blocks (one wave), 128 threads/block,
// 8 outputs per thread (4 rows x 2 cols), k-major double-buffered SMEM.
__global__ __launch_bounds__(128) void gemm_sym_kernel(const float* __restrict__ P) {
    if (blockIdx.x == 0 && threadIdx.x == 0) d_acc = 0.0f;

    // Map linear bid -> upper-triangle (bi, bj), bi <= bj.
    int bi = 0, rem = blockIdx.x;
    #pragma unroll
    for (int r = 0; r < NTILE; r++) {
        int cnt = NTILE - r;
        if (rem >= cnt) { rem -= cnt; bi++; } else break;
    }
    const int bj = bi + rem;
    const int row0 = bi * 32, col0 = bj * 32;

    __shared__ float As[2][KC][PAD];
    __shared__ float Bs[2][KC][PAD];
    __shared__ float Ct[32][33];

    const int tid = threadIdx.x;
    const int tx = tid & 15;          // 0..15 -> col pair
    const int ty = tid >> 4;          // 0..7  -> row quad
    const int lrow = tid >> 2;        // 0..31 load row
    const int lk = (tid & 3) * 4;     // 0,4,8,12 load k offset

    float acc[4][2];
    #pragma unroll
    for (int m = 0; m < 4; m++) { acc[m][0] = 0.f; acc[m][1] = 0.f; }

    // Preload chunk 0
    float4 ra = *reinterpret_cast<const float4*>(&P[(row0 + lrow) * N + lk]);
    float4 rb = *reinterpret_cast<const float4*>(&P[(col0 + lrow) * N + lk]);
    {
        As[0][lk + 0][lrow] = ra.x; As[0][lk + 1][lrow] = ra.y;
        As[0][lk + 2][lrow] = ra.z; As[0][lk + 3][lrow] = ra.w;
        Bs[0][lk + 0][lrow] = rb.x; Bs[0][lk + 1][lrow] = rb.y;
        Bs[0][lk + 2][lrow] = rb.z; Bs[0][lk + 3][lrow] = rb.w;
    }
    __syncthreads();

    for (int c = 0; c < NCHUNK; c++) {
        const int cur = c & 1;
        if (c + 1 < NCHUNK) {
            const int k0 = (c + 1) * KC;
            ra = *reinterpret_cast<const float4*>(&P[(row0 + lrow) * N + k0 + lk]);
            rb = *reinterpret_cast<const float4*>(&P[(col0 + lrow) * N + k0 + lk]);
        }
        #pragma unroll
        for (int kk = 0; kk < KC; kk++) {
            const float4 a = *reinterpret_cast<const float4*>(&As[cur][kk][ty * 4]);
            const float2 b = *reinterpret_cast<const float2*>(&Bs[cur][kk][tx * 2]);
            acc[0][0] = fmaf(a.x, b.x, acc[0][0]); acc[0][1] = fmaf(a.x, b.y, acc[0][1]);
            acc[1][0] = fmaf(a.y, b.x, acc[1][0]); acc[1][1] = fmaf(a.y, b.y, acc[1][1]);
            acc[2][0] = fmaf(a.z, b.x, acc[2][0]); acc[2][1] = fmaf(a.z, b.y, acc[2][1]);
            acc[3][0] = fmaf(a.w, b.x, acc[3][0]); acc[3][1] = fmaf(a.w, b.y, acc[3][1]);
        }
        if (c + 1 < NCHUNK) {
            const int nxt = cur ^ 1;
            As[nxt][lk + 0][lrow] = ra.x; As[nxt][lk + 1][lrow] = ra.y;
            As[nxt][lk + 2][lrow] = ra.z; As[nxt][lk + 3][lrow] = ra.w;
            Bs[nxt][lk + 0][lrow] = rb.x; Bs[nxt][lk + 1][lrow] = rb.y;
            Bs[nxt][lk + 2][lrow] = rb.z; Bs[nxt][lk + 3][lrow] = rb.w;
        }
        __syncthreads();
    }

    // Write C tile (coalesced float2 per thread-row).
    #pragma unroll
    for (int m = 0; m < 4; m++) {
        float2 v = make_float2(acc[m][0], acc[m][1]);
        *reinterpret_cast<float2*>(&d_sim[(row0 + ty * 4 + m) * N + col0 + tx * 2]) = v;
    }

    // Off-diagonal: also write the transpose via SMEM staging.
    if (bi != bj) {
        #pragma unroll
        for (int m = 0; m < 4; m++) {
            Ct[tx * 2 + 0][ty * 4 + m] = acc[m][0];
            Ct[tx * 2 + 1][ty * 4 + m] = acc[m][1];
        }
        __syncthreads();
        #pragma unroll
        for (int idx = tid; idx < 1024; idx += 128) {
            const int r2 = idx >> 5, c2 = idx & 31;
            d_sim[(col0 + r2) * N + row0 + c2] = Ct[r2][c2];
        }
    }
}

// --- Kernel 2: SmoothAP body, positives-only ------------------------------
// sim_pos_rk[i,j] == 0 unless j == i or labels[j] == labels[i]:
// only ~9 of 512 j's per anchor need the k-reduction.
__global__ __launch_bounds__(NB) void smoothap_kernel(const int* __restrict__ labels,
                                                      float* __restrict__ out) {
    const int i = blockIdx.x;
    const int t = threadIdx.x;

    __shared__ float s[N];       // sim row i
    __shared__ float pflag[N];   // positive mask (1/0)
    __shared__ int   jlist[N];   // jlist[0] = i, then positive indices
    __shared__ int   cnt;        // m+1
    __shared__ float ssum;       // sum of ratios over needed j

    if (t == 0) { cnt = 1; ssum = 0.0f; jlist[0] = i; }
    __syncthreads();

    const int li = labels[i];
    #pragma unroll
    for (int k = t; k < N; k += NB) {
        s[k] = d_sim[i * N + k];
        const bool p = (labels[k] == li) && (k != i);
        pflag[k] = p ? 1.0f : 0.0f;
        if (p) { int idx = atomicAdd(&cnt, 1); jlist[idx] = k; }
    }
    __syncthreads();

    const int m1 = cnt;                 // n_pos = m + 1
    const int lane = t & 31, w = t >> 5;

    for (int jj = w; jj < m1; jj += NB / 32) {
        const int j = jlist[jj];
        const float sj = s[j];
        float sa = 0.0f, sp = 0.0f;
        #pragma unroll
        for (int it = 0; it < N / 32; it++) {
            const int k = lane + it * 32;
            float g = sig100(s[k] - sj);
            g = (k == j) ? 0.0f : g;    // (1-eye)[j,k] mask
            sa += g;
            sp = fmaf(g, pflag[k], sp);
        }
        #pragma unroll
        for (int o = 16; o; o >>= 1) {
            sa += __shfl_xor_sync(0xFFFFFFFFu, sa, o);
            sp += __shfl_xor_sync(0xFFFFFFFFu, sp, o);
        }
        if (lane == 0) {
            const float ratio = (jj == 0) ? 1.0f / (1.0f + sa)
                                          : (1.0f + sp) / (1.0f + sa);
            atomicAdd(&ssum, ratio);
        }
    }
    __syncthreads();

    if (t == 0) {
        const float pa = (m1 > 1) ? ssum / (float)m1 : 0.0f;  // where(n_pos>1)
        atomicAdd(&d_acc, pa);
        __threadfence();
        const unsigned old = atomicInc(&d_done, N - 1);       // wraps to 0
        if (old == N - 1) {
            const float acc = atomicAdd(&d_acc, 0.0f);        // coherent read
            out[0] = 1.0f - acc / (float)N;
        }
    }
}

extern "C" void kernel_launch(void* const* d_in, const int* in_sizes, int n_in,
                              void* d_out, int out_size) {
    const float* preds = (const float*)d_in[0];
    const int* labels = (const int*)d_in[1];
    float* out = (float*)d_out;

    gemm_sym_kernel<<<NBLK, 128>>>(preds);
    smoothap_kernel<<<N, NB>>>(labels, out);
}